// round 1
// baseline (speedup 1.0000x reference)
#include <cuda_runtime.h>
#include <cstdint>
#include <cstddef>

// Problem dims
#define BATCH 64
#define EDIM 2048
#define HDIM 1024
#define SLEN 512
#define VOCAB 32000

// ---------------- scratch (device globals; no allocation allowed) ----------------
__device__ float d_xT [EDIM * BATCH];          // x^T   [2048][64]
__device__ float d_h0T[HDIM * BATCH];          // h0^T  [1024][64]
__device__ float d_m  [BATCH * HDIM];          // m     [64][1024]
__device__ float d_mT [HDIM * BATCH];          // m^T   [1024][64]
__device__ float d_hc [BATCH * 2 * HDIM];      // [h | context]  [64][2048]
__device__ float d_hcT[2 * HDIM * BATCH];      // hc^T [2048][64]
__device__ float d_sc [BATCH * SLEN];          // scores/attn [64][512]
__device__ float d_P1 [8 * BATCH * HDIM];      // split-K partials x@Wmx
__device__ float d_P2 [8 * BATCH * HDIM];      // split-K partials h0@Wmh
__device__ float d_P3 [8 * BATCH * 4 * HDIM];  // split-K partials x@Wx
__device__ float d_P4 [8 * BATCH * 4 * HDIM];  // split-K partials m@Wm

// ---------------- 64-row transpose: A[64][K] -> At[K][64] ----------------
__global__ void transpose64(const float* __restrict__ A, float* __restrict__ At, int K) {
    __shared__ float tile[32][33];
    int kb = blockIdx.x * 32;
    int mb = blockIdx.y * 32;
    int tx = threadIdx.x, ty = threadIdx.y;  // 32 x 8
#pragma unroll
    for (int i = 0; i < 32; i += 8)
        tile[ty + i][tx] = A[(size_t)(mb + ty + i) * K + kb + tx];
    __syncthreads();
#pragma unroll
    for (int i = 0; i < 32; i += 8)
        At[(size_t)(kb + ty + i) * 64 + mb + tx] = tile[tx][ty + i];
}

// ---------------- GEMM: C[64][N] = At^T @ W (+bias) ----------------
// At: [K][64] (pre-transposed A), W: [K][N] row-major.
// gridDim.x = N/128, gridDim.y = split-K count (K/Sy divisible by 32).
// If gridDim.y > 1: writes partial sums at C + blockIdx.y*64*N (bias must be null).
// Inner loop uses packed fma.rn.f32x2 (FFMA2) -> 2x fp32 throughput vs FFMA.
__global__ __launch_bounds__(128) void gemm64(
    const float* __restrict__ At, const float* __restrict__ W, int K,
    const float* __restrict__ bias, float* __restrict__ C, int N)
{
    __shared__ float As[32][64];
    __shared__ float Bs[32][128];

    const int tid = threadIdx.x;
    const int col = tid & 15;   // N-direction thread coord (x8 floats)
    const int row = tid >> 4;   // M-direction thread coord (x8 rows)
    const int n0  = blockIdx.x * 128;

    const int Sy   = gridDim.y;
    const int Kc   = K / Sy;
    const int kbeg = blockIdx.y * Kc;
    float* Cb = (Sy > 1) ? (C + (size_t)blockIdx.y * 64 * N) : C;

    unsigned long long acc[8][4];
#pragma unroll
    for (int i = 0; i < 8; i++)
#pragma unroll
        for (int j = 0; j < 4; j++) acc[i][j] = 0ULL;

    for (int k0 = kbeg; k0 < kbeg + Kc; k0 += 32) {
        // A tile: 32 rows x 64 floats, coalesced float4, conflict-free store
#pragma unroll
        for (int p = 0; p < 4; p++) {
            int idx = p * 128 + tid;
            int r = idx >> 4;
            int c = (idx & 15) << 2;
            *(float4*)&As[r][c] = *(const float4*)(At + (size_t)(k0 + r) * 64 + c);
        }
        // B tile: 32 rows x 128 floats
#pragma unroll
        for (int p = 0; p < 8; p++) {
            int idx = p * 128 + tid;
            int r = idx >> 5;
            int c = (idx & 31) << 2;
            *(float4*)&Bs[r][c] = *(const float4*)(W + (size_t)(k0 + r) * N + n0 + c);
        }
        __syncthreads();
#pragma unroll 8
        for (int kk = 0; kk < 32; kk++) {
            float4 a0 = *(const float4*)&As[kk][row * 8];
            float4 a1 = *(const float4*)&As[kk][row * 8 + 4];
            ulonglong2 bq0 = *(const ulonglong2*)&Bs[kk][col * 8];
            ulonglong2 bq1 = *(const ulonglong2*)&Bs[kk][col * 8 + 4];
            float a[8] = {a0.x, a0.y, a0.z, a0.w, a1.x, a1.y, a1.z, a1.w};
#pragma unroll
            for (int i = 0; i < 8; i++) {
                unsigned long long ap;
                asm("mov.b64 %0, {%1, %1};" : "=l"(ap) : "r"(__float_as_uint(a[i])));
                asm("fma.rn.f32x2 %0, %1, %2, %0;" : "+l"(acc[i][0]) : "l"(ap), "l"(bq0.x));
                asm("fma.rn.f32x2 %0, %1, %2, %0;" : "+l"(acc[i][1]) : "l"(ap), "l"(bq0.y));
                asm("fma.rn.f32x2 %0, %1, %2, %0;" : "+l"(acc[i][2]) : "l"(ap), "l"(bq1.x));
                asm("fma.rn.f32x2 %0, %1, %2, %0;" : "+l"(acc[i][3]) : "l"(ap), "l"(bq1.y));
            }
        }
        __syncthreads();
    }
    // epilogue
#pragma unroll
    for (int i = 0; i < 8; i++) {
        int m = row * 8 + i;
#pragma unroll
        for (int j = 0; j < 4; j++) {
            int n = n0 + col * 8 + j * 2;
            float2 v;
            unsigned int ulo, uhi;
            asm("mov.b64 {%0, %1}, %2;" : "=r"(ulo), "=r"(uhi) : "l"(acc[i][j]));
            v.x = __uint_as_float(ulo);
            v.y = __uint_as_float(uhi);
            if (bias) { v.x += bias[n]; v.y += bias[n + 1]; }
            *(float2*)(Cb + (size_t)m * N + n) = v;
        }
    }
}

// ---------------- m = (x@Wmx + bmx) * (h0@Wmh + bmh), reducing split-K partials ----------------
__global__ void m_kernel(const float* __restrict__ P1, const float* __restrict__ P2,
                         const float* __restrict__ bmx, const float* __restrict__ bmh,
                         float* __restrict__ m) {
    int idx = blockIdx.x * 256 + threadIdx.x;  // 65536 total
    int j = idx & (HDIM - 1);
    float a = bmx[j], b = bmh[j];
#pragma unroll
    for (int s = 0; s < 8; s++) {
        a += P1[s * (BATCH * HDIM) + idx];
        b += P2[s * (BATCH * HDIM) + idx];
    }
    m[idx] = a * b;
}

// ---------------- gates: reduce g partials, LSTM cell -> h into hc[:, :H] ----------------
__global__ void gates_kernel(const float* __restrict__ P3, const float* __restrict__ P4,
                             const float* __restrict__ bx, const float* __restrict__ bm,
                             const float* __restrict__ c0, float* __restrict__ hc) {
    int idx = blockIdx.x * 256 + threadIdx.x;  // 65536 = 64*1024
    int b = idx >> 10, j = idx & (HDIM - 1);
    float gv[4];
#pragma unroll
    for (int q = 0; q < 4; q++) {
        int colq = j + q * HDIM;
        float g = bx[colq] + bm[colq];
        size_t off = (size_t)b * (4 * HDIM) + colq;
#pragma unroll
        for (int s = 0; s < 8; s++)
            g += P3[(size_t)s * (BATCH * 4 * HDIM) + off] + P4[(size_t)s * (BATCH * 4 * HDIM) + off];
        gv[q] = g;
    }
    float f  = 1.f / (1.f + expf(-gv[0]));
    float ii = 1.f / (1.f + expf(-gv[1]));
    float o  = 1.f / (1.f + expf(-gv[2]));
    float ct = tanhf(gv[3]);
    float c  = f * c0[idx] + ii * ct;
    hc[(size_t)b * (2 * HDIM) + j] = o * tanhf(c);
}

// ---------------- attention scores: scores[b][s] = dot(h[b], sv[b][s]) ----------------
__global__ void scores_kernel(const float* __restrict__ hc, const float* __restrict__ sv,
                              float* __restrict__ scores) {
    __shared__ float hs[HDIM];
    int b = blockIdx.x;
    int tid = threadIdx.x;                 // 256 threads = 8 warps
    ((float4*)hs)[tid] = ((const float4*)(hc + (size_t)b * (2 * HDIM)))[tid];
    __syncthreads();
    int warp = tid >> 5, lane = tid & 31;
#pragma unroll
    for (int si = 0; si < 8; si++) {
        int s = blockIdx.y * 64 + warp * 8 + si;
        const float4* sp = (const float4*)(sv + ((size_t)b * SLEN + s) * HDIM);
        float acc = 0.f;
#pragma unroll
        for (int i = 0; i < 8; i++) {
            float4 v  = sp[lane + 32 * i];
            float4 hv = ((const float4*)hs)[lane + 32 * i];
            acc += v.x * hv.x + v.y * hv.y + v.z * hv.z + v.w * hv.w;
        }
#pragma unroll
        for (int off = 16; off; off >>= 1) acc += __shfl_xor_sync(0xffffffffu, acc, off);
        if (lane == 0) scores[(size_t)b * SLEN + s] = acc;
    }
}

// ---------------- softmax over 512, in place ----------------
__global__ void softmax_kernel(float* __restrict__ scores) {
    __shared__ float red[8];
    int b = blockIdx.x;
    float* rowp = scores + (size_t)b * SLEN;
    int tid = threadIdx.x;  // 256
    float v0 = rowp[tid], v1 = rowp[tid + 256];
    float mx = fmaxf(v0, v1);
#pragma unroll
    for (int off = 16; off; off >>= 1) mx = fmaxf(mx, __shfl_xor_sync(0xffffffffu, mx, off));
    if ((tid & 31) == 0) red[tid >> 5] = mx;
    __syncthreads();
    float m = red[0];
#pragma unroll
    for (int i = 1; i < 8; i++) m = fmaxf(m, red[i]);
    float e0 = expf(v0 - m), e1 = expf(v1 - m);
    float sum = e0 + e1;
#pragma unroll
    for (int off = 16; off; off >>= 1) sum += __shfl_xor_sync(0xffffffffu, sum, off);
    __syncthreads();
    if ((tid & 31) == 0) red[tid >> 5] = sum;
    __syncthreads();
    float tot = 0.f;
#pragma unroll
    for (int i = 0; i < 8; i++) tot += red[i];
    float inv = 1.f / tot;
    rowp[tid] = e0 * inv;
    rowp[tid + 256] = e1 * inv;
}

// ---------------- context[b][d] = sum_s attn[b][s] * sv[b][s][d] -> hc[:, H:2H] ----------------
__global__ void context_kernel(const float* __restrict__ attn, const float* __restrict__ sv,
                               float* __restrict__ hc) {
    __shared__ float a[SLEN];
    int b = blockIdx.x;
    int tid = threadIdx.x;  // 256
    a[tid] = attn[(size_t)b * SLEN + tid];
    a[tid + 256] = attn[(size_t)b * SLEN + 256 + tid];
    __syncthreads();
    int d = blockIdx.y * 256 + tid;
    const float* svb = sv + (size_t)b * SLEN * HDIM + d;
    float acc0 = 0.f, acc1 = 0.f, acc2 = 0.f, acc3 = 0.f;
    for (int s = 0; s < SLEN; s += 4) {
        acc0 += a[s + 0] * svb[(size_t)(s + 0) * HDIM];
        acc1 += a[s + 1] * svb[(size_t)(s + 1) * HDIM];
        acc2 += a[s + 2] * svb[(size_t)(s + 2) * HDIM];
        acc3 += a[s + 3] * svb[(size_t)(s + 3) * HDIM];
    }
    hc[(size_t)b * (2 * HDIM) + HDIM + d] = (acc0 + acc1) + (acc2 + acc3);
}

// ---------------- launch ----------------
extern "C" void kernel_launch(void* const* d_in, const int* in_sizes, int n_in,
                              void* d_out, int out_size) {
    const float* x    = (const float*)d_in[0];
    const float* h0   = (const float*)d_in[1];
    const float* c0   = (const float*)d_in[2];
    const float* sv   = (const float*)d_in[3];
    const float* Wmx  = (const float*)d_in[4];
    const float* bmx  = (const float*)d_in[5];
    const float* Wmh  = (const float*)d_in[6];
    const float* bmh  = (const float*)d_in[7];
    const float* Wx   = (const float*)d_in[8];
    const float* bx   = (const float*)d_in[9];
    const float* Wm   = (const float*)d_in[10];
    const float* bm   = (const float*)d_in[11];
    const float* Wout = (const float*)d_in[12];
    const float* bout = (const float*)d_in[13];
    float* out = (float*)d_out;

    float *xT, *h0T, *m, *mT, *hc, *hcT, *sc, *P1, *P2, *P3, *P4;
    cudaGetSymbolAddress((void**)&xT,  d_xT);
    cudaGetSymbolAddress((void**)&h0T, d_h0T);
    cudaGetSymbolAddress((void**)&m,   d_m);
    cudaGetSymbolAddress((void**)&mT,  d_mT);
    cudaGetSymbolAddress((void**)&hc,  d_hc);
    cudaGetSymbolAddress((void**)&hcT, d_hcT);
    cudaGetSymbolAddress((void**)&sc,  d_sc);
    cudaGetSymbolAddress((void**)&P1,  d_P1);
    cudaGetSymbolAddress((void**)&P2,  d_P2);
    cudaGetSymbolAddress((void**)&P3,  d_P3);
    cudaGetSymbolAddress((void**)&P4,  d_P4);

    dim3 tb(32, 8);
    // transposes of activations
    transpose64<<<dim3(EDIM / 32, 2), tb>>>(x, xT, EDIM);
    transpose64<<<dim3(HDIM / 32, 2), tb>>>(h0, h0T, HDIM);

    // t1 = x@Wmx (split-K 8), t2 = h0@Wmh (split-K 8)
    gemm64<<<dim3(HDIM / 128, 8), 128>>>(xT,  Wmx, EDIM, nullptr, P1, HDIM);
    gemm64<<<dim3(HDIM / 128, 8), 128>>>(h0T, Wmh, HDIM, nullptr, P2, HDIM);
    m_kernel<<<(BATCH * HDIM) / 256, 256>>>(P1, P2, bmx, bmh, m);
    transpose64<<<dim3(HDIM / 32, 2), tb>>>(m, mT, HDIM);

    // g = x@Wx + m@Wm (+biases in gates kernel), split-K 8 each
    gemm64<<<dim3(4 * HDIM / 128, 8), 128>>>(xT, Wx, EDIM, nullptr, P3, 4 * HDIM);
    gemm64<<<dim3(4 * HDIM / 128, 8), 128>>>(mT, Wm, HDIM, nullptr, P4, 4 * HDIM);
    gates_kernel<<<(BATCH * HDIM) / 256, 256>>>(P3, P4, bx, bm, c0, hc);

    // attention
    scores_kernel<<<dim3(BATCH, 8), 256>>>(hc, sv, sc);
    softmax_kernel<<<BATCH, 256>>>(sc);
    context_kernel<<<dim3(BATCH, HDIM / 256), 256>>>(sc, sv, hc);

    // logits = [h|context] @ Wout + bout
    transpose64<<<dim3(2 * HDIM / 32, 2), tb>>>(hc, hcT, 2 * HDIM);
    gemm64<<<dim3(VOCAB / 128, 1), 128>>>(hcT, Wout, 2 * HDIM, bout, out, VOCAB);
}